// round 2
// baseline (speedup 1.0000x reference)
#include <cuda_runtime.h>
#include <cuda_bf16.h>
#include <math.h>

// Problem constants
#define BATCH 8
#define CCH   256
#define HH    32
#define WW    32
#define NPIX  1024          // H*W
#define DHEAD 32
#define OC_ALL 320          // 32 q + 32 k + 256 v
#define AUGD  34            // d + 2
#define QSTRIDE 36          // padded row stride for q'/k'

// Scratch (device globals: no allocation allowed)
__device__ float g_Wall[OC_ALL * CCH];
__device__ float g_ball[OC_ALL];
__device__ float g_P[BATCH * OC_ALL * NPIX];          // projections (b, oc, n)
__device__ float g_qa[BATCH * NPIX * QSTRIDE];        // augmented scaled q rows
__device__ float g_ka[BATCH * NPIX * QSTRIDE];        // augmented k rows
__device__ float g_attn[BATCH * NPIX * NPIX];         // softmax probs (b, i, j)

// ---------------------------------------------------------------------------
// 0) Pack Wq/Wk/Wv into one 320x256 matrix + bias vector
// ---------------------------------------------------------------------------
__global__ void prep_kernel(const float* __restrict__ Wq, const float* __restrict__ bq,
                            const float* __restrict__ Wk, const float* __restrict__ bk,
                            const float* __restrict__ Wv, const float* __restrict__ bv) {
    int row = blockIdx.x;          // 0..319
    int k   = threadIdx.x;         // 0..255
    const float* src; const float* bs; int r;
    if (row < 32)       { src = Wq; bs = bq; r = row; }
    else if (row < 64)  { src = Wk; bs = bk; r = row - 32; }
    else                { src = Wv; bs = bv; r = row - 64; }
    g_Wall[row * CCH + k] = src[r * CCH + k];
    if (k == 0) g_ball[row] = bs[r];
}

// ---------------------------------------------------------------------------
// 1) Projection GEMM: P[b] (320x1024) = Wall (320x256) @ X_b (256x1024) + bias
//    128x128 tile, BK=8, 8x8 per thread, 256 threads
// ---------------------------------------------------------------------------
#define BM 128
#define BN 128
#define BK 8

__global__ __launch_bounds__(256) void proj_gemm(const float* __restrict__ x) {
    int b  = blockIdx.z;
    int m0 = blockIdx.y * BM;
    int n0 = blockIdx.x * BN;
    const float* X  = x + (size_t)b * CCH * NPIX;
    float*       Cp = g_P + (size_t)b * OC_ALL * NPIX;

    __shared__ float As[BK][BM];
    __shared__ float Bs[BK][BN];

    int tid = threadIdx.x;
    int tx = tid & 15, ty = tid >> 4;
    float acc[8][8];
    #pragma unroll
    for (int i = 0; i < 8; i++)
        #pragma unroll
        for (int j = 0; j < 8; j++) acc[i][j] = 0.f;

    for (int k0 = 0; k0 < CCH; k0 += BK) {
        // A tile: 128 rows x 8 k (transposed into As)
        {
            int row = tid >> 1, kq = (tid & 1) * 4;
            int gm = m0 + row;
            float4 v = (gm < OC_ALL)
                ? *(const float4*)&g_Wall[gm * CCH + k0 + kq]
                : make_float4(0.f, 0.f, 0.f, 0.f);
            As[kq + 0][row] = v.x; As[kq + 1][row] = v.y;
            As[kq + 2][row] = v.z; As[kq + 3][row] = v.w;
        }
        // B tile: 8 k-rows x 128 n (coalesced float4)
        {
            int kr = tid >> 5, nq = (tid & 31) * 4;
            *(float4*)&Bs[kr][nq] = *(const float4*)&X[(size_t)(k0 + kr) * NPIX + n0 + nq];
        }
        __syncthreads();
        #pragma unroll
        for (int k = 0; k < BK; k++) {
            float4 a0 = *(float4*)&As[k][ty * 8];
            float4 a1 = *(float4*)&As[k][ty * 8 + 4];
            float4 b0 = *(float4*)&Bs[k][tx * 8];
            float4 b1 = *(float4*)&Bs[k][tx * 8 + 4];
            float ra[8] = {a0.x, a0.y, a0.z, a0.w, a1.x, a1.y, a1.z, a1.w};
            float rb[8] = {b0.x, b0.y, b0.z, b0.w, b1.x, b1.y, b1.z, b1.w};
            #pragma unroll
            for (int i = 0; i < 8; i++)
                #pragma unroll
                for (int j = 0; j < 8; j++) acc[i][j] += ra[i] * rb[j];
        }
        __syncthreads();
    }
    #pragma unroll
    for (int i = 0; i < 8; i++) {
        int gm = m0 + ty * 8 + i;
        if (gm >= OC_ALL) continue;
        float bias = g_ball[gm];
        float* crow = &Cp[(size_t)gm * NPIX + n0 + tx * 8];
        float4 o0 = make_float4(acc[i][0] + bias, acc[i][1] + bias, acc[i][2] + bias, acc[i][3] + bias);
        float4 o1 = make_float4(acc[i][4] + bias, acc[i][5] + bias, acc[i][6] + bias, acc[i][7] + bias);
        *(float4*)&crow[0] = o0;
        *(float4*)&crow[4] = o1;
    }
}

// ---------------------------------------------------------------------------
// 2) Augment: q'_i = scale*[q_i, q_i.Wr0, q_i.Wr1], k'_j = [k_j, -c0_j, -c1_j]
// ---------------------------------------------------------------------------
__global__ void augment_kernel(const float* __restrict__ Wr) {
    int idx = blockIdx.x * blockDim.x + threadIdx.x;   // 0..8191
    int b = idx >> 10, n = idx & 1023;
    const float* Pb = g_P + (size_t)b * OC_ALL * NPIX;

    float q[DHEAD];
    float a0 = 0.f, a1 = 0.f;
    #pragma unroll
    for (int d = 0; d < DHEAD; d++) {
        q[d] = Pb[d * NPIX + n];
        a0 += q[d] * Wr[2 * d];
        a1 += q[d] * Wr[2 * d + 1];
    }
    const float scale = rsqrtf((float)DHEAD);
    float* qrow = g_qa + (size_t)(b * NPIX + n) * QSTRIDE;
    #pragma unroll
    for (int d = 0; d < DHEAD; d++) qrow[d] = q[d] * scale;
    qrow[32] = a0 * scale;
    qrow[33] = a1 * scale;
    qrow[34] = 0.f; qrow[35] = 0.f;

    float* krow = g_ka + (size_t)(b * NPIX + n) * QSTRIDE;
    #pragma unroll
    for (int d = 0; d < DHEAD; d++) krow[d] = Pb[(32 + d) * NPIX + n];
    int hi = n >> 5, wi = n & 31;
    krow[32] = -(float)hi * (1.f / 31.f);
    krow[33] = -(float)wi * (1.f / 31.f);
    krow[34] = 0.f; krow[35] = 0.f;
}

// ---------------------------------------------------------------------------
// 3) Scores + softmax: 16 rows per block, warp handles 2 rows.
//    k' tile transposed in smem (conflict-free), s-buffer in smem.
// ---------------------------------------------------------------------------
#define SROWS 16
#define JTILE 128
#define KAS_LD 132
#define SCORES_SMEM ((SROWS * NPIX + AUGD * KAS_LD) * (int)sizeof(float))

__global__ __launch_bounds__(256) void scores_kernel() {
    int b  = blockIdx.y;
    int i0 = blockIdx.x * SROWS;
    extern __shared__ float sm[];
    float* sbuf = sm;                    // SROWS * 1024
    float* kas  = sm + SROWS * NPIX;     // AUGD * KAS_LD (transposed tile)

    int tid = threadIdx.x, warp = tid >> 5, lane = tid & 31;
    const float* qab = g_qa + (size_t)b * NPIX * QSTRIDE;
    const float* kab = g_ka + (size_t)b * NPIX * QSTRIDE;

    // each warp owns rows r0, r0+1; hold q' in registers
    int r0 = i0 + warp * 2;
    float q0[AUGD], q1[AUGD];
    #pragma unroll
    for (int t = 0; t < AUGD; t++) {
        q0[t] = qab[(size_t)r0 * QSTRIDE + t];
        q1[t] = qab[(size_t)(r0 + 1) * QSTRIDE + t];
    }

    for (int j0 = 0; j0 < NPIX; j0 += JTILE) {
        __syncthreads();
        // load k' tile transposed: kas[t][jj]
        for (int idx = tid; idx < JTILE * AUGD; idx += 256) {
            int jj = idx / AUGD, t = idx % AUGD;
            kas[t * KAS_LD + jj] = kab[(size_t)(j0 + jj) * QSTRIDE + t];
        }
        __syncthreads();
        #pragma unroll
        for (int s = 0; s < 4; s++) {
            int j = s * 32 + lane;
            float acc0 = 0.f, acc1 = 0.f;
            #pragma unroll
            for (int t = 0; t < AUGD; t++) {
                float kv = kas[t * KAS_LD + j];
                acc0 += q0[t] * kv;
                acc1 += q1[t] * kv;
            }
            sbuf[(warp * 2) * NPIX + j0 + j]     = acc0;
            sbuf[(warp * 2 + 1) * NPIX + j0 + j] = acc1;
        }
    }
    __syncthreads();

    // softmax per row + write probs
    float* attnb = g_attn + (size_t)b * NPIX * NPIX;
    #pragma unroll
    for (int rr = 0; rr < 2; rr++) {
        int lrow = warp * 2 + rr;
        int grow = i0 + lrow;
        float* srow = sbuf + lrow * NPIX;
        float m = -1e30f;
        for (int k = lane; k < NPIX; k += 32) m = fmaxf(m, srow[k]);
        #pragma unroll
        for (int off = 16; off; off >>= 1) m = fmaxf(m, __shfl_xor_sync(0xffffffffu, m, off));
        float sum = 0.f;
        for (int k = lane; k < NPIX; k += 32) {
            float e = __expf(srow[k] - m);
            srow[k] = e;
            sum += e;
        }
        #pragma unroll
        for (int off = 16; off; off >>= 1) sum += __shfl_xor_sync(0xffffffffu, sum, off);
        float inv = 1.f / sum;
        for (int k = lane; k < NPIX; k += 32)
            attnb[(size_t)grow * NPIX + k] = srow[k] * inv;
    }
}

// ---------------------------------------------------------------------------
// 4) Output GEMM (NT): out[b,c,i] = gamma * sum_j V[b,c,j]*attn[b,i,j] + x[b,c,i]
// ---------------------------------------------------------------------------
__global__ __launch_bounds__(256) void out_gemm(const float* __restrict__ x,
                                                const float* __restrict__ gamma,
                                                float* __restrict__ out) {
    int b  = blockIdx.z;
    int m0 = blockIdx.y * BM;      // channel tile (M=256)
    int n0 = blockIdx.x * BN;      // pixel tile (N=1024)
    const float* V     = g_P + (size_t)b * OC_ALL * NPIX + (size_t)64 * NPIX;  // 256x1024
    const float* attnb = g_attn + (size_t)b * NPIX * NPIX;

    __shared__ float As[BK][BM];
    __shared__ float Bs[BK][BN];

    int tid = threadIdx.x;
    int tx = tid & 15, ty = tid >> 4;
    float acc[8][8];
    #pragma unroll
    for (int i = 0; i < 8; i++)
        #pragma unroll
        for (int j = 0; j < 8; j++) acc[i][j] = 0.f;

    for (int k0 = 0; k0 < NPIX; k0 += BK) {
        {   // A = V rows (k contiguous)
            int row = tid >> 1, kq = (tid & 1) * 4;
            float4 v = *(const float4*)&V[(size_t)(m0 + row) * NPIX + k0 + kq];
            As[kq + 0][row] = v.x; As[kq + 1][row] = v.y;
            As[kq + 2][row] = v.z; As[kq + 3][row] = v.w;
        }
        {   // B = attn rows (k=j contiguous), transposed into Bs[k][n]
            int row = tid >> 1, kq = (tid & 1) * 4;
            float4 v = *(const float4*)&attnb[(size_t)(n0 + row) * NPIX + k0 + kq];
            Bs[kq + 0][row] = v.x; Bs[kq + 1][row] = v.y;
            Bs[kq + 2][row] = v.z; Bs[kq + 3][row] = v.w;
        }
        __syncthreads();
        #pragma unroll
        for (int k = 0; k < BK; k++) {
            float4 a0 = *(float4*)&As[k][ty * 8];
            float4 a1 = *(float4*)&As[k][ty * 8 + 4];
            float4 b0 = *(float4*)&Bs[k][tx * 8];
            float4 b1 = *(float4*)&Bs[k][tx * 8 + 4];
            float ra[8] = {a0.x, a0.y, a0.z, a0.w, a1.x, a1.y, a1.z, a1.w};
            float rb[8] = {b0.x, b0.y, b0.z, b0.w, b1.x, b1.y, b1.z, b1.w};
            #pragma unroll
            for (int i = 0; i < 8; i++)
                #pragma unroll
                for (int j = 0; j < 8; j++) acc[i][j] += ra[i] * rb[j];
        }
        __syncthreads();
    }

    float g = gamma[0];
    #pragma unroll
    for (int i = 0; i < 8; i++) {
        int gm = m0 + ty * 8 + i;
        size_t base = ((size_t)b * CCH + gm) * NPIX + n0 + tx * 8;
        float4 x0 = *(const float4*)&x[base];
        float4 x1 = *(const float4*)&x[base + 4];
        float4 o0 = make_float4(g * acc[i][0] + x0.x, g * acc[i][1] + x0.y,
                                g * acc[i][2] + x0.z, g * acc[i][3] + x0.w);
        float4 o1 = make_float4(g * acc[i][4] + x1.x, g * acc[i][5] + x1.y,
                                g * acc[i][6] + x1.z, g * acc[i][7] + x1.w);
        *(float4*)&out[base]     = o0;
        *(float4*)&out[base + 4] = o1;
    }
}

// ---------------------------------------------------------------------------
extern "C" void kernel_launch(void* const* d_in, const int* in_sizes, int n_in,
                              void* d_out, int out_size) {
    const float* x     = (const float*)d_in[0];
    const float* Wq    = (const float*)d_in[1];
    const float* bq    = (const float*)d_in[2];
    const float* Wk    = (const float*)d_in[3];
    const float* bk    = (const float*)d_in[4];
    const float* Wv    = (const float*)d_in[5];
    const float* bv    = (const float*)d_in[6];
    const float* Wr    = (const float*)d_in[7];
    const float* gamma = (const float*)d_in[9];
    float* out = (float*)d_out;

    cudaFuncSetAttribute(scores_kernel, cudaFuncAttributeMaxDynamicSharedMemorySize, SCORES_SMEM);

    prep_kernel<<<OC_ALL, CCH>>>(Wq, bq, Wk, bk, Wv, bv);
    proj_gemm<<<dim3(NPIX / BN, (OC_ALL + BM - 1) / BM, BATCH), 256>>>(x);
    augment_kernel<<<(BATCH * NPIX) / 256, 256>>>(Wr);
    scores_kernel<<<dim3(NPIX / SROWS, BATCH), 256, SCORES_SMEM>>>();
    out_gemm<<<dim3(NPIX / BN, CCH / BM, BATCH), 256>>>(x, gamma, out);
}

// round 4
// speedup vs baseline: 2.0095x; 2.0095x over previous
#include <cuda_runtime.h>
#include <cuda_bf16.h>
#include <math.h>
#include <cstdint>

// Problem constants
#define BATCH 8
#define CCH   256
#define HH    32
#define WW    32
#define NPIX  1024          // H*W
#define DHEAD 32
#define OC_ALL 320          // 32 q + 32 k + 256 v
#define AUGD  34            // d + 2
#define QSTRIDE 36          // padded row stride for q'/k'

// Scratch (device globals: no allocation allowed)
__device__ float g_Wall[384 * CCH];                   // padded to 384 rows (tile math)
__device__ float g_ball[OC_ALL];
__device__ float g_P[BATCH * OC_ALL * NPIX];          // projections (b, oc, n)
__device__ float g_qa[BATCH * NPIX * QSTRIDE];        // augmented scaled q rows
__device__ float g_ka[BATCH * NPIX * QSTRIDE];        // augmented k rows
__device__ float g_attn[BATCH * NPIX * NPIX];         // softmax probs (b, i, j)

// ===========================================================================
// mma.sync tf32 helpers (portable PTX; compiles for sm_103 non-'a' target)
// ===========================================================================
__device__ __forceinline__ float f2tf32(float f) {
    uint32_t u;
    asm("cvt.rna.tf32.f32 %0, %1;" : "=r"(u) : "f"(f));
    return __uint_as_float(u);
}
__device__ __forceinline__ float4 cvt4(float4 v) {
    v.x = f2tf32(v.x); v.y = f2tf32(v.y); v.z = f2tf32(v.z); v.w = f2tf32(v.w);
    return v;
}
// D(16x8) += A(16x8) * B(8x8); A row-major, B col-major fragments
__device__ __forceinline__ void mma_tf32(float* d, const uint32_t* a, const uint32_t* b) {
    asm volatile(
        "mma.sync.aligned.m16n8k8.row.col.f32.tf32.tf32.f32 "
        "{%0,%1,%2,%3}, {%4,%5,%6,%7}, {%8,%9}, {%0,%1,%2,%3};\n"
        : "+f"(d[0]), "+f"(d[1]), "+f"(d[2]), "+f"(d[3])
        : "r"(a[0]), "r"(a[1]), "r"(a[2]), "r"(a[3]), "r"(b[0]), "r"(b[1]));
}

// ---------------------------------------------------------------------------
// 0) Pack Wq/Wk/Wv into one 320x256 matrix + bias vector
// ---------------------------------------------------------------------------
__global__ void prep_kernel(const float* __restrict__ Wq, const float* __restrict__ bq,
                            const float* __restrict__ Wk, const float* __restrict__ bk,
                            const float* __restrict__ Wv, const float* __restrict__ bv) {
    int row = blockIdx.x;          // 0..383
    int k   = threadIdx.x;         // 0..255
    if (row >= OC_ALL) {           // zero the pad rows (avoid NaN garbage in mma)
        g_Wall[row * CCH + k] = 0.f;
        return;
    }
    const float* src; const float* bs; int r;
    if (row < 32)       { src = Wq; bs = bq; r = row; }
    else if (row < 64)  { src = Wk; bs = bk; r = row - 32; }
    else                { src = Wv; bs = bv; r = row - 64; }
    g_Wall[row * CCH + k] = src[r * CCH + k];
    if (k == 0) g_ball[row] = bs[r];
}

// ---------------------------------------------------------------------------
// 1) Projection GEMM (tf32 mma): P[b](320x1024) = Wall(320x256) @ X_b(256x1024) + bias
//    Block tile 128x128, BK=32 (8 chunks), 8 warps of 64x32, double-buffered.
//    A staged m-major stride 36 (conflict-free frags); B staged k-major stride 136.
// ---------------------------------------------------------------------------
#define ASTR 36
#define BSTR_P 136
#define PROJ_SMEM ((2 * 128 * ASTR + 2 * 32 * BSTR_P) * (int)sizeof(float))

__global__ __launch_bounds__(256) void proj_gemm_mma(const float* __restrict__ x) {
    int b  = blockIdx.z;
    int m0 = blockIdx.y * 128;
    int n0 = blockIdx.x * 128;
    const float* X  = x + (size_t)b * CCH * NPIX;
    float*       Cp = g_P + (size_t)b * OC_ALL * NPIX;

    extern __shared__ float sm[];
    float* As = sm;                      // 2 stages x 128 x 36
    float* Bs = sm + 2 * 128 * ASTR;     // 2 stages x 32 x 136

    int tid = threadIdx.x, warp = tid >> 5, lane = tid & 31;
    int wm = warp >> 2, wn = warp & 3;   // warp tile: rows wm*64, cols wn*32
    int g = lane >> 2, tg = lane & 3;

    float acc[4][4][4];
    #pragma unroll
    for (int i = 0; i < 4; i++)
        #pragma unroll
        for (int j = 0; j < 4; j++)
            #pragma unroll
            for (int r = 0; r < 4; r++) acc[i][j][r] = 0.f;

    // staging index precompute
    int arow[4], akq[4], brow[4], bnq[4];
    #pragma unroll
    for (int u = 0; u < 4; u++) {
        int idx = tid + u * 256;
        arow[u] = idx >> 3;  akq[u] = (idx & 7) * 4;    // A: 128x32
        brow[u] = idx >> 5;  bnq[u] = (idx & 31) * 4;   // B: 32x128
    }

    float4 pa[4], pb[4];
    // prologue: chunk 0
    #pragma unroll
    for (int u = 0; u < 4; u++) {
        pa[u] = *(const float4*)&g_Wall[(m0 + arow[u]) * CCH + akq[u]];
        pb[u] = *(const float4*)&X[(size_t)brow[u] * NPIX + n0 + bnq[u]];
    }
    #pragma unroll
    for (int u = 0; u < 4; u++) {
        *(float4*)&As[arow[u] * ASTR + akq[u]]   = cvt4(pa[u]);
        *(float4*)&Bs[brow[u] * BSTR_P + bnq[u]] = cvt4(pb[u]);
    }
    __syncthreads();

    #pragma unroll 1
    for (int t = 0; t < 8; t++) {           // K = 256 / 32
        if (t < 7) {
            int k0 = (t + 1) * 32;
            #pragma unroll
            for (int u = 0; u < 4; u++) {
                pa[u] = *(const float4*)&g_Wall[(m0 + arow[u]) * CCH + k0 + akq[u]];
                pb[u] = *(const float4*)&X[(size_t)(k0 + brow[u]) * NPIX + n0 + bnq[u]];
            }
        }
        const float* A = As + (t & 1) * 128 * ASTR;
        const float* B = Bs + (t & 1) * 32 * BSTR_P;
        #pragma unroll
        for (int kk = 0; kk < 32; kk += 8) {
            uint32_t af[4][4], bf[4][2];
            #pragma unroll
            for (int mt = 0; mt < 4; mt++) {
                int r = wm * 64 + mt * 16 + g;
                af[mt][0] = __float_as_uint(A[r * ASTR + kk + tg]);
                af[mt][1] = __float_as_uint(A[(r + 8) * ASTR + kk + tg]);
                af[mt][2] = __float_as_uint(A[r * ASTR + kk + tg + 4]);
                af[mt][3] = __float_as_uint(A[(r + 8) * ASTR + kk + tg + 4]);
            }
            #pragma unroll
            for (int nt = 0; nt < 4; nt++) {
                int nc = wn * 32 + nt * 8 + g;
                bf[nt][0] = __float_as_uint(B[(kk + tg) * BSTR_P + nc]);
                bf[nt][1] = __float_as_uint(B[(kk + tg + 4) * BSTR_P + nc]);
            }
            #pragma unroll
            for (int mt = 0; mt < 4; mt++)
                #pragma unroll
                for (int nt = 0; nt < 4; nt++)
                    mma_tf32(acc[mt][nt], af[mt], bf[nt]);
        }
        if (t < 7) {
            float* An = As + ((t + 1) & 1) * 128 * ASTR;
            float* Bn = Bs + ((t + 1) & 1) * 32 * BSTR_P;
            #pragma unroll
            for (int u = 0; u < 4; u++) {
                *(float4*)&An[arow[u] * ASTR + akq[u]]   = cvt4(pa[u]);
                *(float4*)&Bn[brow[u] * BSTR_P + bnq[u]] = cvt4(pb[u]);
            }
        }
        __syncthreads();
    }

    // epilogue: add bias, store (guard rows >= 320)
    #pragma unroll
    for (int mt = 0; mt < 4; mt++) {
        int r0 = m0 + wm * 64 + mt * 16 + g;
        int r1 = r0 + 8;
        #pragma unroll
        for (int nt = 0; nt < 4; nt++) {
            int c = n0 + wn * 32 + nt * 8 + 2 * tg;
            if (r0 < OC_ALL) {
                float bias = g_ball[r0];
                float2 o = make_float2(acc[mt][nt][0] + bias, acc[mt][nt][1] + bias);
                *(float2*)&Cp[(size_t)r0 * NPIX + c] = o;
            }
            if (r1 < OC_ALL) {
                float bias = g_ball[r1];
                float2 o = make_float2(acc[mt][nt][2] + bias, acc[mt][nt][3] + bias);
                *(float2*)&Cp[(size_t)r1 * NPIX + c] = o;
            }
        }
    }
}

// ---------------------------------------------------------------------------
// 2) Augment: q'_i = scale*[q_i, q_i.Wr0, q_i.Wr1], k'_j = [k_j, -c0_j, -c1_j]
// ---------------------------------------------------------------------------
__global__ void augment_kernel(const float* __restrict__ Wr) {
    int idx = blockIdx.x * blockDim.x + threadIdx.x;
    int b = idx >> 10, n = idx & 1023;
    const float* Pb = g_P + (size_t)b * OC_ALL * NPIX;

    float q[DHEAD];
    float a0 = 0.f, a1 = 0.f;
    #pragma unroll
    for (int d = 0; d < DHEAD; d++) {
        q[d] = Pb[d * NPIX + n];
        a0 += q[d] * Wr[2 * d];
        a1 += q[d] * Wr[2 * d + 1];
    }
    const float scale = rsqrtf((float)DHEAD);
    float* qrow = g_qa + (size_t)(b * NPIX + n) * QSTRIDE;
    #pragma unroll
    for (int d = 0; d < DHEAD; d++) qrow[d] = q[d] * scale;
    qrow[32] = a0 * scale;
    qrow[33] = a1 * scale;
    qrow[34] = 0.f; qrow[35] = 0.f;

    float* krow = g_ka + (size_t)(b * NPIX + n) * QSTRIDE;
    #pragma unroll
    for (int d = 0; d < DHEAD; d++) krow[d] = Pb[(32 + d) * NPIX + n];
    int hi = n >> 5, wi = n & 31;
    krow[32] = -(float)hi * (1.f / 31.f);
    krow[33] = -(float)wi * (1.f / 31.f);
    krow[34] = 0.f; krow[35] = 0.f;
}

// ---------------------------------------------------------------------------
// 3) Scores + softmax (unchanged; next round's target)
// ---------------------------------------------------------------------------
#define SROWS 16
#define JTILE 128
#define KAS_LD 132
#define SCORES_SMEM ((SROWS * NPIX + AUGD * KAS_LD) * (int)sizeof(float))

__global__ __launch_bounds__(256) void scores_kernel() {
    int b  = blockIdx.y;
    int i0 = blockIdx.x * SROWS;
    extern __shared__ float sm[];
    float* sbuf = sm;
    float* kas  = sm + SROWS * NPIX;

    int tid = threadIdx.x, warp = tid >> 5, lane = tid & 31;
    const float* qab = g_qa + (size_t)b * NPIX * QSTRIDE;
    const float* kab = g_ka + (size_t)b * NPIX * QSTRIDE;

    int r0 = i0 + warp * 2;
    float q0[AUGD], q1[AUGD];
    #pragma unroll
    for (int t = 0; t < AUGD; t++) {
        q0[t] = qab[(size_t)r0 * QSTRIDE + t];
        q1[t] = qab[(size_t)(r0 + 1) * QSTRIDE + t];
    }

    for (int j0 = 0; j0 < NPIX; j0 += JTILE) {
        __syncthreads();
        for (int idx = tid; idx < JTILE * AUGD; idx += 256) {
            int jj = idx / AUGD, t = idx % AUGD;
            kas[t * KAS_LD + jj] = kab[(size_t)(j0 + jj) * QSTRIDE + t];
        }
        __syncthreads();
        #pragma unroll
        for (int s = 0; s < 4; s++) {
            int j = s * 32 + lane;
            float acc0 = 0.f, acc1 = 0.f;
            #pragma unroll
            for (int t = 0; t < AUGD; t++) {
                float kv = kas[t * KAS_LD + j];
                acc0 += q0[t] * kv;
                acc1 += q1[t] * kv;
            }
            sbuf[(warp * 2) * NPIX + j0 + j]     = acc0;
            sbuf[(warp * 2 + 1) * NPIX + j0 + j] = acc1;
        }
    }
    __syncthreads();

    float* attnb = g_attn + (size_t)b * NPIX * NPIX;
    #pragma unroll
    for (int rr = 0; rr < 2; rr++) {
        int lrow = warp * 2 + rr;
        int grow = i0 + lrow;
        float* srow = sbuf + lrow * NPIX;
        float m = -1e30f;
        for (int k = lane; k < NPIX; k += 32) m = fmaxf(m, srow[k]);
        #pragma unroll
        for (int off = 16; off; off >>= 1) m = fmaxf(m, __shfl_xor_sync(0xffffffffu, m, off));
        float sum = 0.f;
        for (int k = lane; k < NPIX; k += 32) {
            float e = __expf(srow[k] - m);
            srow[k] = e;
            sum += e;
        }
        #pragma unroll
        for (int off = 16; off; off >>= 1) sum += __shfl_xor_sync(0xffffffffu, sum, off);
        float inv = 1.f / sum;
        for (int k = lane; k < NPIX; k += 32)
            attnb[(size_t)grow * NPIX + k] = srow[k] * inv;
    }
}

// ---------------------------------------------------------------------------
// 4) Output GEMM (tf32 mma): out[b,c,i] = gamma * sum_j V[b,c,j]*attn[b,i,j] + x
//    D = V(128xK) @ attn_tile(128xK)^T. Both operands n/m-major with K contig
//    -> both staged stride-36, no transpose, conflict-free fragment LDS.
// ---------------------------------------------------------------------------
#define OUT_SMEM (2 * 2 * 128 * ASTR * (int)sizeof(float))

__global__ __launch_bounds__(256) void out_gemm_mma(const float* __restrict__ x,
                                                    const float* __restrict__ gamma,
                                                    float* __restrict__ out) {
    int b  = blockIdx.z;
    int m0 = blockIdx.y * 128;     // channel tile
    int n0 = blockIdx.x * 128;     // pixel-i tile
    const float* V     = g_P + (size_t)b * OC_ALL * NPIX + (size_t)64 * NPIX;
    const float* attnb = g_attn + (size_t)b * NPIX * NPIX;

    extern __shared__ float sm[];
    float* As = sm;                    // 2 x 128 x 36 (V rows)
    float* Bs = sm + 2 * 128 * ASTR;   // 2 x 128 x 36 (attn rows)

    int tid = threadIdx.x, warp = tid >> 5, lane = tid & 31;
    int wm = warp >> 2, wn = warp & 3;
    int g = lane >> 2, tg = lane & 3;

    float acc[4][4][4];
    #pragma unroll
    for (int i = 0; i < 4; i++)
        #pragma unroll
        for (int j = 0; j < 4; j++)
            #pragma unroll
            for (int r = 0; r < 4; r++) acc[i][j][r] = 0.f;

    int srow[4], skq[4];
    #pragma unroll
    for (int u = 0; u < 4; u++) {
        int idx = tid + u * 256;
        srow[u] = idx >> 3; skq[u] = (idx & 7) * 4;
    }

    float4 pa[4], pb[4];
    #pragma unroll
    for (int u = 0; u < 4; u++) {
        pa[u] = *(const float4*)&V[(size_t)(m0 + srow[u]) * NPIX + skq[u]];
        pb[u] = *(const float4*)&attnb[(size_t)(n0 + srow[u]) * NPIX + skq[u]];
    }
    #pragma unroll
    for (int u = 0; u < 4; u++) {
        *(float4*)&As[srow[u] * ASTR + skq[u]] = cvt4(pa[u]);
        *(float4*)&Bs[srow[u] * ASTR + skq[u]] = cvt4(pb[u]);
    }
    __syncthreads();

    #pragma unroll 1
    for (int t = 0; t < 32; t++) {          // K = 1024 / 32
        if (t < 31) {
            int k0 = (t + 1) * 32;
            #pragma unroll
            for (int u = 0; u < 4; u++) {
                pa[u] = *(const float4*)&V[(size_t)(m0 + srow[u]) * NPIX + k0 + skq[u]];
                pb[u] = *(const float4*)&attnb[(size_t)(n0 + srow[u]) * NPIX + k0 + skq[u]];
            }
        }
        const float* A = As + (t & 1) * 128 * ASTR;
        const float* B = Bs + (t & 1) * 128 * ASTR;
        #pragma unroll
        for (int kk = 0; kk < 32; kk += 8) {
            uint32_t af[4][4], bf[4][2];
            #pragma unroll
            for (int mt = 0; mt < 4; mt++) {
                int r = wm * 64 + mt * 16 + g;
                af[mt][0] = __float_as_uint(A[r * ASTR + kk + tg]);
                af[mt][1] = __float_as_uint(A[(r + 8) * ASTR + kk + tg]);
                af[mt][2] = __float_as_uint(A[r * ASTR + kk + tg + 4]);
                af[mt][3] = __float_as_uint(A[(r + 8) * ASTR + kk + tg + 4]);
            }
            #pragma unroll
            for (int nt = 0; nt < 4; nt++) {
                int nr = wn * 32 + nt * 8 + g;
                bf[nt][0] = __float_as_uint(B[nr * ASTR + kk + tg]);
                bf[nt][1] = __float_as_uint(B[nr * ASTR + kk + tg + 4]);
            }
            #pragma unroll
            for (int mt = 0; mt < 4; mt++)
                #pragma unroll
                for (int nt = 0; nt < 4; nt++)
                    mma_tf32(acc[mt][nt], af[mt], bf[nt]);
        }
        if (t < 31) {
            float* An = As + ((t + 1) & 1) * 128 * ASTR;
            float* Bn = Bs + ((t + 1) & 1) * 128 * ASTR;
            #pragma unroll
            for (int u = 0; u < 4; u++) {
                *(float4*)&An[srow[u] * ASTR + skq[u]] = cvt4(pa[u]);
                *(float4*)&Bn[srow[u] * ASTR + skq[u]] = cvt4(pb[u]);
            }
        }
        __syncthreads();
    }

    // epilogue: out = gamma*acc + x (float2 stores)
    float gv = gamma[0];
    #pragma unroll
    for (int mt = 0; mt < 4; mt++) {
        int r0 = m0 + wm * 64 + mt * 16 + g;
        #pragma unroll
        for (int nt = 0; nt < 4; nt++) {
            int c = n0 + wn * 32 + nt * 8 + 2 * tg;
            size_t base0 = ((size_t)b * CCH + r0) * NPIX + c;
            size_t base1 = base0 + (size_t)8 * NPIX;
            float2 x0 = *(const float2*)&x[base0];
            float2 x1 = *(const float2*)&x[base1];
            float2 o0 = make_float2(gv * acc[mt][nt][0] + x0.x, gv * acc[mt][nt][1] + x0.y);
            float2 o1 = make_float2(gv * acc[mt][nt][2] + x1.x, gv * acc[mt][nt][3] + x1.y);
            *(float2*)&out[base0] = o0;
            *(float2*)&out[base1] = o1;
        }
    }
}

// ---------------------------------------------------------------------------
extern "C" void kernel_launch(void* const* d_in, const int* in_sizes, int n_in,
                              void* d_out, int out_size) {
    const float* x     = (const float*)d_in[0];
    const float* Wq    = (const float*)d_in[1];
    const float* bq    = (const float*)d_in[2];
    const float* Wk    = (const float*)d_in[3];
    const float* bk    = (const float*)d_in[4];
    const float* Wv    = (const float*)d_in[5];
    const float* bv    = (const float*)d_in[6];
    const float* Wr    = (const float*)d_in[7];
    const float* gamma = (const float*)d_in[9];
    float* out = (float*)d_out;

    cudaFuncSetAttribute(scores_kernel, cudaFuncAttributeMaxDynamicSharedMemorySize, SCORES_SMEM);
    cudaFuncSetAttribute(proj_gemm_mma, cudaFuncAttributeMaxDynamicSharedMemorySize, PROJ_SMEM);
    cudaFuncSetAttribute(out_gemm_mma, cudaFuncAttributeMaxDynamicSharedMemorySize, OUT_SMEM);

    prep_kernel<<<384, CCH>>>(Wq, bq, Wk, bk, Wv, bv);
    proj_gemm_mma<<<dim3(NPIX / 128, 3, BATCH), 256, PROJ_SMEM>>>(x);
    augment_kernel<<<(BATCH * NPIX) / 256, 256>>>(Wr);
    scores_kernel<<<dim3(NPIX / SROWS, BATCH), 256, SCORES_SMEM>>>();
    out_gemm_mma<<<dim3(NPIX / 128, CCH / 128, BATCH), 256, OUT_SMEM>>>(x, gamma, out);
}

// round 6
// speedup vs baseline: 2.4521x; 1.2202x over previous
#include <cuda_runtime.h>
#include <cuda_bf16.h>
#include <math.h>
#include <cstdint>

// Problem constants
#define BATCH 8
#define CCH   256
#define NPIX  1024
#define DHEAD 32
#define OC_ALL 320          // 32 q + 32 k + 256 v
#define KA    40            // augmented K padded to 40 (34 used)
#define ASTR2 44            // row stride for q'/k' (conflict-free frags)

// Scratch (device globals)
__device__ float g_Wall[384 * CCH];
__device__ float g_ball[OC_ALL];
__device__ float g_P[BATCH * OC_ALL * NPIX];          // projections (b, oc, n)
__device__ float g_qa[BATCH * NPIX * ASTR2];          // augmented scaled q rows (tf32)
__device__ float g_ka[BATCH * NPIX * ASTR2];          // augmented k rows (tf32)

// ===========================================================================
// helpers
// ===========================================================================
__device__ __forceinline__ float f2tf32(float f) {
    uint32_t u;
    asm("cvt.rna.tf32.f32 %0, %1;" : "=r"(u) : "f"(f));
    return __uint_as_float(u);
}
__device__ __forceinline__ float4 cvt4(float4 v) {
    v.x = f2tf32(v.x); v.y = f2tf32(v.y); v.z = f2tf32(v.z); v.w = f2tf32(v.w);
    return v;
}
__device__ __forceinline__ void mma_tf32(float* d, const uint32_t* a, const uint32_t* b) {
    asm volatile(
        "mma.sync.aligned.m16n8k8.row.col.f32.tf32.tf32.f32 "
        "{%0,%1,%2,%3}, {%4,%5,%6,%7}, {%8,%9}, {%0,%1,%2,%3};\n"
        : "+f"(d[0]), "+f"(d[1]), "+f"(d[2]), "+f"(d[3])
        : "r"(a[0]), "r"(a[1]), "r"(a[2]), "r"(a[3]), "r"(b[0]), "r"(b[1]));
}
// FFMA-pipe exp (exp2 bit trick + deg-4 poly), |err| ~1e-6 rel
__device__ __forceinline__ float exp_poly(float v) {
    float t = v * 1.4426950408889634f;
    float r = t + 12582912.0f;               // round-to-nearest via magic
    int   i = __float_as_int(r);
    float jf = r - 12582912.0f;
    float f  = t - jf;
    float p = 0.0096181291f;
    p = fmaf(p, f, 0.055504109f);
    p = fmaf(p, f, 0.24022651f);
    p = fmaf(p, f, 0.69314718f);
    p = fmaf(p, f, 1.0f);
    return __int_as_float(__float_as_int(p) + (i << 23));
}

// ---------------------------------------------------------------------------
// 0) Pack Wq/Wk/Wv into one 320x256 (padded 384) matrix + bias vector
// ---------------------------------------------------------------------------
__global__ void prep_kernel(const float* __restrict__ Wq, const float* __restrict__ bq,
                            const float* __restrict__ Wk, const float* __restrict__ bk,
                            const float* __restrict__ Wv, const float* __restrict__ bv) {
    int row = blockIdx.x;
    int k   = threadIdx.x;
    if (row >= OC_ALL) { g_Wall[row * CCH + k] = 0.f; return; }
    const float* src; const float* bs; int r;
    if (row < 32)       { src = Wq; bs = bq; r = row; }
    else if (row < 64)  { src = Wk; bs = bk; r = row - 32; }
    else                { src = Wv; bs = bv; r = row - 64; }
    g_Wall[row * CCH + k] = src[r * CCH + k];
    if (k == 0) g_ball[row] = bs[r];
}

// ---------------------------------------------------------------------------
// 1) Projection GEMM (tf32 mma) — unchanged from round 4 (passing)
// ---------------------------------------------------------------------------
#define ASTR 36
#define BSTR_P 136
#define PROJ_SMEM ((2 * 128 * ASTR + 2 * 32 * BSTR_P) * (int)sizeof(float))

__global__ __launch_bounds__(256) void proj_gemm_mma(const float* __restrict__ x) {
    int b  = blockIdx.z;
    int m0 = blockIdx.y * 128;
    int n0 = blockIdx.x * 128;
    const float* X  = x + (size_t)b * CCH * NPIX;
    float*       Cp = g_P + (size_t)b * OC_ALL * NPIX;

    extern __shared__ float sm[];
    float* As = sm;
    float* Bs = sm + 2 * 128 * ASTR;

    int tid = threadIdx.x, warp = tid >> 5, lane = tid & 31;
    int wm = warp >> 2, wn = warp & 3;
    int g = lane >> 2, tg = lane & 3;

    float acc[4][4][4];
    #pragma unroll
    for (int i = 0; i < 4; i++)
        #pragma unroll
        for (int j = 0; j < 4; j++)
            #pragma unroll
            for (int r = 0; r < 4; r++) acc[i][j][r] = 0.f;

    int arow[4], akq[4], brow[4], bnq[4];
    #pragma unroll
    for (int u = 0; u < 4; u++) {
        int idx = tid + u * 256;
        arow[u] = idx >> 3;  akq[u] = (idx & 7) * 4;
        brow[u] = idx >> 5;  bnq[u] = (idx & 31) * 4;
    }

    float4 pa[4], pb[4];
    #pragma unroll
    for (int u = 0; u < 4; u++) {
        pa[u] = *(const float4*)&g_Wall[(m0 + arow[u]) * CCH + akq[u]];
        pb[u] = *(const float4*)&X[(size_t)brow[u] * NPIX + n0 + bnq[u]];
    }
    #pragma unroll
    for (int u = 0; u < 4; u++) {
        *(float4*)&As[arow[u] * ASTR + akq[u]]   = cvt4(pa[u]);
        *(float4*)&Bs[brow[u] * BSTR_P + bnq[u]] = cvt4(pb[u]);
    }
    __syncthreads();

    #pragma unroll 1
    for (int t = 0; t < 8; t++) {
        if (t < 7) {
            int k0 = (t + 1) * 32;
            #pragma unroll
            for (int u = 0; u < 4; u++) {
                pa[u] = *(const float4*)&g_Wall[(m0 + arow[u]) * CCH + k0 + akq[u]];
                pb[u] = *(const float4*)&X[(size_t)(k0 + brow[u]) * NPIX + n0 + bnq[u]];
            }
        }
        const float* A = As + (t & 1) * 128 * ASTR;
        const float* B = Bs + (t & 1) * 32 * BSTR_P;
        #pragma unroll
        for (int kk = 0; kk < 32; kk += 8) {
            uint32_t af[4][4], bf[4][2];
            #pragma unroll
            for (int mt = 0; mt < 4; mt++) {
                int r = wm * 64 + mt * 16 + g;
                af[mt][0] = __float_as_uint(A[r * ASTR + kk + tg]);
                af[mt][1] = __float_as_uint(A[(r + 8) * ASTR + kk + tg]);
                af[mt][2] = __float_as_uint(A[r * ASTR + kk + tg + 4]);
                af[mt][3] = __float_as_uint(A[(r + 8) * ASTR + kk + tg + 4]);
            }
            #pragma unroll
            for (int nt = 0; nt < 4; nt++) {
                int nc = wn * 32 + nt * 8 + g;
                bf[nt][0] = __float_as_uint(B[(kk + tg) * BSTR_P + nc]);
                bf[nt][1] = __float_as_uint(B[(kk + tg + 4) * BSTR_P + nc]);
            }
            #pragma unroll
            for (int mt = 0; mt < 4; mt++)
                #pragma unroll
                for (int nt = 0; nt < 4; nt++)
                    mma_tf32(acc[mt][nt], af[mt], bf[nt]);
        }
        if (t < 7) {
            float* An = As + ((t + 1) & 1) * 128 * ASTR;
            float* Bn = Bs + ((t + 1) & 1) * 32 * BSTR_P;
            #pragma unroll
            for (int u = 0; u < 4; u++) {
                *(float4*)&An[arow[u] * ASTR + akq[u]]   = cvt4(pa[u]);
                *(float4*)&Bn[brow[u] * BSTR_P + bnq[u]] = cvt4(pb[u]);
            }
        }
        __syncthreads();
    }

    #pragma unroll
    for (int mt = 0; mt < 4; mt++) {
        int r0 = m0 + wm * 64 + mt * 16 + g;
        int r1 = r0 + 8;
        #pragma unroll
        for (int nt = 0; nt < 4; nt++) {
            int c = n0 + wn * 32 + nt * 8 + 2 * tg;
            if (r0 < OC_ALL) {
                float bias = g_ball[r0];
                float2 o = make_float2(acc[mt][nt][0] + bias, acc[mt][nt][1] + bias);
                *(float2*)&Cp[(size_t)r0 * NPIX + c] = o;
            }
            if (r1 < OC_ALL) {
                float bias = g_ball[r1];
                float2 o = make_float2(acc[mt][nt][2] + bias, acc[mt][nt][3] + bias);
                *(float2*)&Cp[(size_t)r1 * NPIX + c] = o;
            }
        }
    }
}

// ---------------------------------------------------------------------------
// 2) Augment: q'_i = scale*[q_i, q.Wr0, q.Wr1, 0..], k'_j = [k_j, -c0, -c1, 0..]
//    stride 44, K padded to 40, tf32-prerounded.
// ---------------------------------------------------------------------------
__global__ void augment_kernel(const float* __restrict__ Wr) {
    int idx = blockIdx.x * blockDim.x + threadIdx.x;
    int b = idx >> 10, n = idx & 1023;
    const float* Pb = g_P + (size_t)b * OC_ALL * NPIX;

    float q[DHEAD];
    float a0 = 0.f, a1 = 0.f;
    #pragma unroll
    for (int d = 0; d < DHEAD; d++) {
        q[d] = Pb[d * NPIX + n];
        a0 += q[d] * Wr[2 * d];
        a1 += q[d] * Wr[2 * d + 1];
    }
    const float scale = rsqrtf((float)DHEAD);
    float* qrow = g_qa + (size_t)(b * NPIX + n) * ASTR2;
    #pragma unroll
    for (int d = 0; d < DHEAD; d++) qrow[d] = f2tf32(q[d] * scale);
    qrow[32] = f2tf32(a0 * scale);
    qrow[33] = f2tf32(a1 * scale);
    #pragma unroll
    for (int d = 34; d < KA; d++) qrow[d] = 0.f;

    float* krow = g_ka + (size_t)(b * NPIX + n) * ASTR2;
    #pragma unroll
    for (int d = 0; d < DHEAD; d++) krow[d] = f2tf32(Pb[(32 + d) * NPIX + n]);
    int hi = n >> 5, wi = n & 31;
    krow[32] = f2tf32(-(float)hi * (1.f / 31.f));
    krow[33] = f2tf32(-(float)wi * (1.f / 31.f));
    #pragma unroll
    for (int d = 34; d < KA; d++) krow[d] = 0.f;
}

// ---------------------------------------------------------------------------
// 3) Fused attention: logits(mma) -> exp (no-max softmax) -> AV (mma) -> out
//    CTA = (64 i-rows, batch). 512 threads (16 warps, 4x4).
// ---------------------------------------------------------------------------
#define IB 64
#define JT 128
#define PSTR 132
// smem float offsets
#define QS_OFF 0
#define KS_OFF (IB * ASTR2)                       // 2816
#define PS_OFF (KS_OFF + JT * ASTR2)              // 8448
#define VS_OFF (PS_OFF + IB * PSTR)               // 16896
#define RS_OFF (VS_OFF + 2 * IB * PSTR)           // 33792
#define RI_OFF (RS_OFF + 64)
#define FUSED_SMEM ((RI_OFF + 64) * (int)sizeof(float))

__global__ __launch_bounds__(512) void fused_attn(const float* __restrict__ x,
                                                  const float* __restrict__ gamma,
                                                  float* __restrict__ out) {
    int b  = blockIdx.y;
    int i0 = blockIdx.x * IB;
    const float* qab = g_qa + (size_t)b * NPIX * ASTR2;
    const float* kab = g_ka + (size_t)b * NPIX * ASTR2;
    const float* V   = g_P + (size_t)b * OC_ALL * NPIX + (size_t)64 * NPIX;  // [256,1024]

    extern __shared__ float sm[];
    float* Qs = sm + QS_OFF;
    float* Ks = sm + KS_OFF;
    float* Ps = sm + PS_OFF;
    float* Vs = sm + VS_OFF;
    float* rs = sm + RS_OFF;
    float* ri = sm + RI_OFF;

    int tid = threadIdx.x, warp = tid >> 5, lane = tid & 31;
    int wq = warp >> 2, wr = warp & 3;          // 4x4 warp grid
    int g = lane >> 2, tg = lane & 3;

    if (tid < 64) rs[tid] = 0.f;

    // stage Qs (64 x 40, stride 44)
    for (int idx = tid; idx < 640; idx += 512) {
        int row = idx / 10, c4 = (idx % 10) * 4;
        *(float4*)&Qs[row * ASTR2 + c4] = *(const float4*)&qab[(size_t)(i0 + row) * ASTR2 + c4];
    }

    float accO[4][2][4];
    #pragma unroll
    for (int c = 0; c < 4; c++)
        #pragma unroll
        for (int nt = 0; nt < 2; nt++)
            #pragma unroll
            for (int r = 0; r < 4; r++) accO[c][nt][r] = 0.f;
    float s0 = 0.f, s1 = 0.f;

    #pragma unroll 1
    for (int jt = 0; jt < 8; jt++) {
        int j0 = jt * JT;
        // stage Ks (128 x 40)
        for (int idx = tid; idx < 1280; idx += 512) {
            int row = idx / 10, c4 = (idx % 10) * 4;
            *(float4*)&Ks[row * ASTR2 + c4] = *(const float4*)&kab[(size_t)(j0 + row) * ASTR2 + c4];
        }
        __syncthreads();

        // logits: 64x128, K=40
        float accS[4][4];
        #pragma unroll
        for (int nt = 0; nt < 4; nt++)
            #pragma unroll
            for (int r = 0; r < 4; r++) accS[nt][r] = 0.f;
        #pragma unroll
        for (int k = 0; k < 5; k++) {
            int kk = k * 8;
            uint32_t af[4];
            int abase = (wq * 16 + g) * ASTR2 + kk + tg;
            af[0] = __float_as_uint(Qs[abase]);
            af[1] = __float_as_uint(Qs[abase + 8 * ASTR2]);
            af[2] = __float_as_uint(Qs[abase + 4]);
            af[3] = __float_as_uint(Qs[abase + 8 * ASTR2 + 4]);
            #pragma unroll
            for (int nt = 0; nt < 4; nt++) {
                uint32_t bf[2];
                int bb = (wr * 32 + nt * 8 + g) * ASTR2 + kk + tg;
                bf[0] = __float_as_uint(Ks[bb]);
                bf[1] = __float_as_uint(Ks[bb + 4]);
                mma_tf32(accS[nt], af, bf);
            }
        }

        // exp (12 MUFU + 4 poly per thread), rowsum, write Ps
        int r0l = wq * 16 + g;
        #pragma unroll
        for (int nt = 0; nt < 4; nt++) {
            float e0, e1, e2, e3;
            if (nt == 3) {
                e0 = exp_poly(accS[nt][0]); e1 = exp_poly(accS[nt][1]);
                e2 = exp_poly(accS[nt][2]); e3 = exp_poly(accS[nt][3]);
            } else {
                e0 = __expf(accS[nt][0]); e1 = __expf(accS[nt][1]);
                e2 = __expf(accS[nt][2]); e3 = __expf(accS[nt][3]);
            }
            s0 += e0 + e1; s1 += e2 + e3;
            int c = wr * 32 + nt * 8 + 2 * tg;
            *(float2*)&Ps[r0l * PSTR + c]       = make_float2(e0, e1);
            *(float2*)&Ps[(r0l + 8) * PSTR + c] = make_float2(e2, e3);
        }

        // AV: 4 chunks of 64 channels, double-buffered Vs
        float4 pv[4];
        #pragma unroll
        for (int u = 0; u < 4; u++) {
            int idx = tid + u * 512;
            int row = idx >> 5, c4 = (idx & 31) * 4;
            pv[u] = *(const float4*)&V[(size_t)row * NPIX + j0 + c4];
        }
        __syncthreads();            // Ps complete; prior readers of Vs done
        #pragma unroll
        for (int u = 0; u < 4; u++) {
            int idx = tid + u * 512;
            int row = idx >> 5, c4 = (idx & 31) * 4;
            *(float4*)&Vs[row * PSTR + c4] = pv[u];
        }
        __syncthreads();

        #pragma unroll 1
        for (int c = 0; c < 4; c++) {
            if (c < 3) {
                #pragma unroll
                for (int u = 0; u < 4; u++) {
                    int idx = tid + u * 512;
                    int row = idx >> 5, c4 = (idx & 31) * 4;
                    pv[u] = *(const float4*)&V[(size_t)((c + 1) * 64 + row) * NPIX + j0 + c4];
                }
            }
            const float* Vc = Vs + (c & 1) * IB * PSTR;
            #pragma unroll
            for (int kk = 0; kk < 128; kk += 8) {
                uint32_t af[4];
                int abase = (wq * 16 + g) * PSTR + kk + tg;
                af[0] = __float_as_uint(Ps[abase]);
                af[1] = __float_as_uint(Ps[abase + 8 * PSTR]);
                af[2] = __float_as_uint(Ps[abase + 4]);
                af[3] = __float_as_uint(Ps[abase + 8 * PSTR + 4]);
                #pragma unroll
                for (int nt = 0; nt < 2; nt++) {
                    uint32_t bf[2];
                    int bb = (wr * 16 + nt * 8 + g) * PSTR + kk + tg;
                    bf[0] = __float_as_uint(Vc[bb]);
                    bf[1] = __float_as_uint(Vc[bb + 4]);
                    mma_tf32(accO[c][nt], af, bf);
                }
            }
            if (c < 3) {
                float* Vn = Vs + ((c + 1) & 1) * IB * PSTR;
                #pragma unroll
                for (int u = 0; u < 4; u++) {
                    int idx = tid + u * 512;
                    int row = idx >> 5, c4 = (idx & 31) * 4;
                    *(float4*)&Vn[row * PSTR + c4] = pv[u];
                }
            }
            __syncthreads();
        }
    }

    // finalize row sums: reduce over tg lanes, then across wr warps
    s0 += __shfl_xor_sync(0xffffffffu, s0, 1);
    s0 += __shfl_xor_sync(0xffffffffu, s0, 2);
    s1 += __shfl_xor_sync(0xffffffffu, s1, 1);
    s1 += __shfl_xor_sync(0xffffffffu, s1, 2);
    if (tg == 0) {
        atomicAdd(&rs[wq * 16 + g], s0);
        atomicAdd(&rs[wq * 16 + 8 + g], s1);
    }
    __syncthreads();
    if (tid < 64) ri[tid] = gamma[0] / rs[tid];
    __syncthreads();

    // epilogue: out[b,c,i] = ri[i] * acc + x[b,c,i]
    int r0l = wq * 16 + g;
    float inv0 = ri[r0l], inv1 = ri[r0l + 8];
    #pragma unroll
    for (int c = 0; c < 4; c++) {
        #pragma unroll
        for (int nt = 0; nt < 2; nt++) {
            int ch = c * 64 + wr * 16 + nt * 8 + 2 * tg;
            size_t b0 = ((size_t)b * CCH + ch) * NPIX + i0 + r0l;
            size_t b1 = b0 + NPIX;                 // ch+1
            out[b0]     = accO[c][nt][0] * inv0 + x[b0];
            out[b1]     = accO[c][nt][1] * inv0 + x[b1];
            out[b0 + 8] = accO[c][nt][2] * inv1 + x[b0 + 8];
            out[b1 + 8] = accO[c][nt][3] * inv1 + x[b1 + 8];
        }
    }
}

// ---------------------------------------------------------------------------
extern "C" void kernel_launch(void* const* d_in, const int* in_sizes, int n_in,
                              void* d_out, int out_size) {
    const float* x     = (const float*)d_in[0];
    const float* Wq    = (const float*)d_in[1];
    const float* bq    = (const float*)d_in[2];
    const float* Wk    = (const float*)d_in[3];
    const float* bk    = (const float*)d_in[4];
    const float* Wv    = (const float*)d_in[5];
    const float* bv    = (const float*)d_in[6];
    const float* Wr    = (const float*)d_in[7];
    const float* gamma = (const float*)d_in[9];
    float* out = (float*)d_out;

    cudaFuncSetAttribute(proj_gemm_mma, cudaFuncAttributeMaxDynamicSharedMemorySize, PROJ_SMEM);
    cudaFuncSetAttribute(fused_attn, cudaFuncAttributeMaxDynamicSharedMemorySize, FUSED_SMEM);

    prep_kernel<<<384, CCH>>>(Wq, bq, Wk, bk, Wv, bv);
    proj_gemm_mma<<<dim3(NPIX / 128, 3, BATCH), 256, PROJ_SMEM>>>(x);
    augment_kernel<<<(BATCH * NPIX) / 256, 256>>>(Wr);
    fused_attn<<<dim3(NPIX / IB, BATCH), 512, FUSED_SMEM>>>(x, gamma, out);
}

// round 7
// speedup vs baseline: 3.5879x; 1.4632x over previous
#include <cuda_runtime.h>
#include <cuda_bf16.h>
#include <math.h>
#include <cstdint>

// Problem constants
#define BATCH 8
#define CCH   256
#define NPIX  1024
#define DHEAD 32
#define OC_ALL 320          // 32 q + 32 k + 256 v
#define KA    40            // augmented K padded to 40 (34 used)
#define ASTR2 44            // row stride for q'/k' (conflict-free tf32 frags)

// Scratch (device globals)
__device__ float g_Wall[384 * CCH];
__device__ float g_ball[OC_ALL];
__device__ float g_P[BATCH * 64 * NPIX];                 // q,k projections (b, 0..63, n)
__device__ __nv_bfloat16 g_Vb[BATCH * CCH * NPIX];       // V projections, bf16
__device__ float g_qa[BATCH * NPIX * ASTR2];             // augmented scaled q rows (tf32)
__device__ float g_ka[BATCH * NPIX * ASTR2];             // augmented k rows (tf32)

// ===========================================================================
// helpers
// ===========================================================================
__device__ __forceinline__ float f2tf32(float f) {
    uint32_t u;
    asm("cvt.rna.tf32.f32 %0, %1;" : "=r"(u) : "f"(f));
    return __uint_as_float(u);
}
__device__ __forceinline__ float4 cvt4(float4 v) {
    v.x = f2tf32(v.x); v.y = f2tf32(v.y); v.z = f2tf32(v.z); v.w = f2tf32(v.w);
    return v;
}
__device__ __forceinline__ void mma_tf32(float* d, const uint32_t* a, const uint32_t* b) {
    asm volatile(
        "mma.sync.aligned.m16n8k8.row.col.f32.tf32.tf32.f32 "
        "{%0,%1,%2,%3}, {%4,%5,%6,%7}, {%8,%9}, {%0,%1,%2,%3};\n"
        : "+f"(d[0]), "+f"(d[1]), "+f"(d[2]), "+f"(d[3])
        : "r"(a[0]), "r"(a[1]), "r"(a[2]), "r"(a[3]), "r"(b[0]), "r"(b[1]));
}
__device__ __forceinline__ void mma_bf16(float* d, const uint32_t* a, const uint32_t* b) {
    asm volatile(
        "mma.sync.aligned.m16n8k16.row.col.f32.bf16.bf16.f32 "
        "{%0,%1,%2,%3}, {%4,%5,%6,%7}, {%8,%9}, {%0,%1,%2,%3};\n"
        : "+f"(d[0]), "+f"(d[1]), "+f"(d[2]), "+f"(d[3])
        : "r"(a[0]), "r"(a[1]), "r"(a[2]), "r"(a[3]), "r"(b[0]), "r"(b[1]));
}

// ---------------------------------------------------------------------------
// 0) Pack Wq/Wk/Wv into one 320x256 (padded 384) matrix + bias vector
// ---------------------------------------------------------------------------
__global__ void prep_kernel(const float* __restrict__ Wq, const float* __restrict__ bq,
                            const float* __restrict__ Wk, const float* __restrict__ bk,
                            const float* __restrict__ Wv, const float* __restrict__ bv) {
    int row = blockIdx.x;
    int k   = threadIdx.x;
    if (row >= OC_ALL) { g_Wall[row * CCH + k] = 0.f; return; }
    const float* src; const float* bs; int r;
    if (row < 32)       { src = Wq; bs = bq; r = row; }
    else if (row < 64)  { src = Wk; bs = bk; r = row - 32; }
    else                { src = Wv; bs = bv; r = row - 64; }
    g_Wall[row * CCH + k] = src[r * CCH + k];
    if (k == 0) g_ball[row] = bs[r];
}

// ---------------------------------------------------------------------------
// 1) Projection GEMM (tf32 mma): q,k rows -> g_P (fp32); v rows -> g_Vb (bf16)
// ---------------------------------------------------------------------------
#define ASTR 36
#define BSTR_P 136
#define PROJ_SMEM ((2 * 128 * ASTR + 2 * 32 * BSTR_P) * (int)sizeof(float))

__global__ __launch_bounds__(256) void proj_gemm_mma(const float* __restrict__ x) {
    int b  = blockIdx.z;
    int m0 = blockIdx.y * 128;
    int n0 = blockIdx.x * 128;
    const float* X  = x + (size_t)b * CCH * NPIX;

    extern __shared__ float sm[];
    float* As = sm;
    float* Bs = sm + 2 * 128 * ASTR;

    int tid = threadIdx.x, warp = tid >> 5, lane = tid & 31;
    int wm = warp >> 2, wn = warp & 3;
    int g = lane >> 2, tg = lane & 3;

    float acc[4][4][4];
    #pragma unroll
    for (int i = 0; i < 4; i++)
        #pragma unroll
        for (int j = 0; j < 4; j++)
            #pragma unroll
            for (int r = 0; r < 4; r++) acc[i][j][r] = 0.f;

    int arow[4], akq[4], brow[4], bnq[4];
    #pragma unroll
    for (int u = 0; u < 4; u++) {
        int idx = tid + u * 256;
        arow[u] = idx >> 3;  akq[u] = (idx & 7) * 4;
        brow[u] = idx >> 5;  bnq[u] = (idx & 31) * 4;
    }

    float4 pa[4], pb[4];
    #pragma unroll
    for (int u = 0; u < 4; u++) {
        pa[u] = *(const float4*)&g_Wall[(m0 + arow[u]) * CCH + akq[u]];
        pb[u] = *(const float4*)&X[(size_t)brow[u] * NPIX + n0 + bnq[u]];
    }
    #pragma unroll
    for (int u = 0; u < 4; u++) {
        *(float4*)&As[arow[u] * ASTR + akq[u]]   = cvt4(pa[u]);
        *(float4*)&Bs[brow[u] * BSTR_P + bnq[u]] = cvt4(pb[u]);
    }
    __syncthreads();

    #pragma unroll 1
    for (int t = 0; t < 8; t++) {
        if (t < 7) {
            int k0 = (t + 1) * 32;
            #pragma unroll
            for (int u = 0; u < 4; u++) {
                pa[u] = *(const float4*)&g_Wall[(m0 + arow[u]) * CCH + k0 + akq[u]];
                pb[u] = *(const float4*)&X[(size_t)(k0 + brow[u]) * NPIX + n0 + bnq[u]];
            }
        }
        const float* A = As + (t & 1) * 128 * ASTR;
        const float* B = Bs + (t & 1) * 32 * BSTR_P;
        #pragma unroll
        for (int kk = 0; kk < 32; kk += 8) {
            uint32_t af[4][4], bf[4][2];
            #pragma unroll
            for (int mt = 0; mt < 4; mt++) {
                int r = wm * 64 + mt * 16 + g;
                af[mt][0] = __float_as_uint(A[r * ASTR + kk + tg]);
                af[mt][1] = __float_as_uint(A[(r + 8) * ASTR + kk + tg]);
                af[mt][2] = __float_as_uint(A[r * ASTR + kk + tg + 4]);
                af[mt][3] = __float_as_uint(A[(r + 8) * ASTR + kk + tg + 4]);
            }
            #pragma unroll
            for (int nt = 0; nt < 4; nt++) {
                int nc = wn * 32 + nt * 8 + g;
                bf[nt][0] = __float_as_uint(B[(kk + tg) * BSTR_P + nc]);
                bf[nt][1] = __float_as_uint(B[(kk + tg + 4) * BSTR_P + nc]);
            }
            #pragma unroll
            for (int mt = 0; mt < 4; mt++)
                #pragma unroll
                for (int nt = 0; nt < 4; nt++)
                    mma_tf32(acc[mt][nt], af[mt], bf[nt]);
        }
        if (t < 7) {
            float* An = As + ((t + 1) & 1) * 128 * ASTR;
            float* Bn = Bs + ((t + 1) & 1) * 32 * BSTR_P;
            #pragma unroll
            for (int u = 0; u < 4; u++) {
                *(float4*)&An[arow[u] * ASTR + akq[u]]   = cvt4(pa[u]);
                *(float4*)&Bn[brow[u] * BSTR_P + bnq[u]] = cvt4(pb[u]);
            }
        }
        __syncthreads();
    }

    // epilogue: q,k rows (<64) -> g_P fp32; v rows (64..319) -> g_Vb bf16
    #pragma unroll
    for (int mt = 0; mt < 4; mt++) {
        int rbase = m0 + wm * 64 + mt * 16 + g;
        #pragma unroll
        for (int half = 0; half < 2; half++) {
            int r = rbase + half * 8;
            if (r >= OC_ALL) continue;
            float bias = g_ball[r];
            #pragma unroll
            for (int nt = 0; nt < 4; nt++) {
                int c = n0 + wn * 32 + nt * 8 + 2 * tg;
                float v0 = acc[mt][nt][half * 2 + 0] + bias;
                float v1 = acc[mt][nt][half * 2 + 1] + bias;
                if (r < 64) {
                    *(float2*)&g_P[((size_t)b * 64 + r) * NPIX + c] = make_float2(v0, v1);
                } else {
                    *(__nv_bfloat162*)&g_Vb[((size_t)b * CCH + (r - 64)) * NPIX + c] =
                        __floats2bfloat162_rn(v0, v1);
                }
            }
        }
    }
}

// ---------------------------------------------------------------------------
// 2) Augment: q'_i = scale*[q_i, q.Wr0, q.Wr1, 0..], k'_j = [k_j, -c0, -c1, 0..]
// ---------------------------------------------------------------------------
__global__ void augment_kernel(const float* __restrict__ Wr) {
    int idx = blockIdx.x * blockDim.x + threadIdx.x;
    int b = idx >> 10, n = idx & 1023;
    const float* Pb = g_P + (size_t)b * 64 * NPIX;

    float q[DHEAD];
    float a0 = 0.f, a1 = 0.f;
    #pragma unroll
    for (int d = 0; d < DHEAD; d++) {
        q[d] = Pb[d * NPIX + n];
        a0 += q[d] * Wr[2 * d];
        a1 += q[d] * Wr[2 * d + 1];
    }
    const float scale = rsqrtf((float)DHEAD);
    float* qrow = g_qa + (size_t)(b * NPIX + n) * ASTR2;
    #pragma unroll
    for (int d = 0; d < DHEAD; d++) qrow[d] = f2tf32(q[d] * scale);
    qrow[32] = f2tf32(a0 * scale);
    qrow[33] = f2tf32(a1 * scale);
    #pragma unroll
    for (int d = 34; d < KA; d++) qrow[d] = 0.f;

    float* krow = g_ka + (size_t)(b * NPIX + n) * ASTR2;
    #pragma unroll
    for (int d = 0; d < DHEAD; d++) krow[d] = f2tf32(Pb[(32 + d) * NPIX + n]);
    int hi = n >> 5, wi = n & 31;
    krow[32] = f2tf32(-(float)hi * (1.f / 31.f));
    krow[33] = f2tf32(-(float)wi * (1.f / 31.f));
    #pragma unroll
    for (int d = 34; d < KA; d++) krow[d] = 0.f;
}

// ---------------------------------------------------------------------------
// 3) Fused attention: logits tf32 mma -> exp (no-max) -> bf16 AV mma -> out
//    CTA = (64 i-rows, batch), 512 threads (16 warps, 4x4).
//    P and V in bf16 (stride 136 halves = conflict-free fragment LDS).
// ---------------------------------------------------------------------------
#define IB 64
#define JT 128
#define PSTRH 136
// byte offsets in dynamic smem
#define QS_B 0
#define KS_B (QS_B + IB * ASTR2 * 4)            // 11264
#define PS_B (KS_B + JT * ASTR2 * 4)            // 33792
#define VS_B (PS_B + IB * PSTRH * 2)            // 51200
#define RS_B (VS_B + CCH * PSTRH * 2)           // 120832
#define RI_B (RS_B + IB * 4)
#define FUSED_SMEM (RI_B + IB * 4)

__global__ __launch_bounds__(512) void fused_attn(const float* __restrict__ x,
                                                  const float* __restrict__ gamma,
                                                  float* __restrict__ out) {
    int b  = blockIdx.y;
    int i0 = blockIdx.x * IB;
    const float* qab = g_qa + (size_t)b * NPIX * ASTR2;
    const float* kab = g_ka + (size_t)b * NPIX * ASTR2;
    const __nv_bfloat16* Vg = g_Vb + (size_t)b * CCH * NPIX;

    extern __shared__ char smc[];
    float* Qs = (float*)(smc + QS_B);
    float* Ks = (float*)(smc + KS_B);
    __nv_bfloat16* PsH = (__nv_bfloat16*)(smc + PS_B);
    __nv_bfloat16* VsH = (__nv_bfloat16*)(smc + VS_B);
    float* rs = (float*)(smc + RS_B);
    float* ri = (float*)(smc + RI_B);

    int tid = threadIdx.x, warp = tid >> 5, lane = tid & 31;
    int wq = warp >> 2, wr = warp & 3;          // 4 (i) x 4 (j/ch) warp grid
    int g = lane >> 2, tg = lane & 3;

    if (tid < IB) rs[tid] = 0.f;

    // stage Qs (64 x 40 fp32, stride 44)
    for (int idx = tid; idx < 640; idx += 512) {
        int row = idx / 10, c4 = (idx % 10) * 4;
        *(float4*)&Qs[row * ASTR2 + c4] = *(const float4*)&qab[(size_t)(i0 + row) * ASTR2 + c4];
    }

    float accO[8][4];
    #pragma unroll
    for (int nt = 0; nt < 8; nt++)
        #pragma unroll
        for (int r = 0; r < 4; r++) accO[nt][r] = 0.f;
    float s0 = 0.f, s1 = 0.f;

    int r0l = wq * 16 + g;

    #pragma unroll 1
    for (int jt = 0; jt < 8; jt++) {
        int j0 = jt * JT;
        // stage Ks (128 x 40 fp32)
        for (int idx = tid; idx < 1280; idx += 512) {
            int row = idx / 10, c4 = (idx % 10) * 4;
            *(float4*)&Ks[row * ASTR2 + c4] = *(const float4*)&kab[(size_t)(j0 + row) * ASTR2 + c4];
        }
        // prefetch V tile (256 ch x 128 j, bf16) into registers
        uint4 pv[8];
        #pragma unroll
        for (int u = 0; u < 8; u++) {
            int idx = tid + u * 512;
            int row = idx >> 4, q8 = (idx & 15) * 8;
            pv[u] = *(const uint4*)&Vg[(size_t)row * NPIX + j0 + q8];
        }
        __syncthreads();   // Ks visible; prev AV fully done

        // logits: 64 x 128, K=40 (tf32)
        float accS[4][4];
        #pragma unroll
        for (int nt = 0; nt < 4; nt++)
            #pragma unroll
            for (int r = 0; r < 4; r++) accS[nt][r] = 0.f;
        #pragma unroll
        for (int k = 0; k < 5; k++) {
            int kk = k * 8;
            uint32_t af[4];
            int abase = r0l * ASTR2 + kk + tg;
            af[0] = __float_as_uint(Qs[abase]);
            af[1] = __float_as_uint(Qs[abase + 8 * ASTR2]);
            af[2] = __float_as_uint(Qs[abase + 4]);
            af[3] = __float_as_uint(Qs[abase + 8 * ASTR2 + 4]);
            #pragma unroll
            for (int nt = 0; nt < 4; nt++) {
                uint32_t bf[2];
                int bb = (wr * 32 + nt * 8 + g) * ASTR2 + kk + tg;
                bf[0] = __float_as_uint(Ks[bb]);
                bf[1] = __float_as_uint(Ks[bb + 4]);
                mma_tf32(accS[nt], af, bf);
            }
        }

        // exp + rowsum + write Ps (bf16 pairs)
        #pragma unroll
        for (int nt = 0; nt < 4; nt++) {
            float e0 = __expf(accS[nt][0]);
            float e1 = __expf(accS[nt][1]);
            float e2 = __expf(accS[nt][2]);
            float e3 = __expf(accS[nt][3]);
            s0 += e0 + e1; s1 += e2 + e3;
            int c = wr * 32 + nt * 8 + 2 * tg;
            *(__nv_bfloat162*)&PsH[r0l * PSTRH + c]       = __floats2bfloat162_rn(e0, e1);
            *(__nv_bfloat162*)&PsH[(r0l + 8) * PSTRH + c] = __floats2bfloat162_rn(e2, e3);
        }
        __syncthreads();   // Ps visible; prev AV Vs reads long done

        // store V tile to smem
        #pragma unroll
        for (int u = 0; u < 8; u++) {
            int idx = tid + u * 512;
            int row = idx >> 4, q8 = (idx & 15) * 8;
            *(uint4*)&VsH[row * PSTRH + q8] = pv[u];
        }
        __syncthreads();   // Vs visible

        // AV: 64 x 256 += Ps(64x128) @ Vs(256x128)^T, bf16 k16
        #pragma unroll
        for (int kk = 0; kk < 128; kk += 16) {
            uint32_t af[4];
            const __nv_bfloat16* pA = PsH + r0l * PSTRH + kk + 2 * tg;
            af[0] = *(const uint32_t*)(pA);
            af[1] = *(const uint32_t*)(pA + 8 * PSTRH);
            af[2] = *(const uint32_t*)(pA + 8);
            af[3] = *(const uint32_t*)(pA + 8 * PSTRH + 8);
            #pragma unroll
            for (int nt = 0; nt < 8; nt++) {
                uint32_t bf[2];
                const __nv_bfloat16* pB = VsH + (wr * 64 + nt * 8 + g) * PSTRH + kk + 2 * tg;
                bf[0] = *(const uint32_t*)(pB);
                bf[1] = *(const uint32_t*)(pB + 8);
                mma_bf16(accO[nt], af, bf);
            }
        }
    }

    // finalize row sums: reduce over tg lanes, then across wr warps
    s0 += __shfl_xor_sync(0xffffffffu, s0, 1);
    s0 += __shfl_xor_sync(0xffffffffu, s0, 2);
    s1 += __shfl_xor_sync(0xffffffffu, s1, 1);
    s1 += __shfl_xor_sync(0xffffffffu, s1, 2);
    if (tg == 0) {
        atomicAdd(&rs[r0l], s0);
        atomicAdd(&rs[r0l + 8], s1);
    }
    __syncthreads();
    if (tid < IB) ri[tid] = gamma[0] / rs[tid];
    __syncthreads();

    // epilogue: out[b,c,i] = ri[i] * acc + x[b,c,i]
    float inv0 = ri[r0l], inv1 = ri[r0l + 8];
    #pragma unroll
    for (int nt = 0; nt < 8; nt++) {
        int ch = wr * 64 + nt * 8 + 2 * tg;
        size_t b0 = ((size_t)b * CCH + ch) * NPIX + i0 + r0l;
        size_t b1 = b0 + NPIX;                 // ch+1
        out[b0]     = accO[nt][0] * inv0 + x[b0];
        out[b1]     = accO[nt][1] * inv0 + x[b1];
        out[b0 + 8] = accO[nt][2] * inv1 + x[b0 + 8];
        out[b1 + 8] = accO[nt][3] * inv1 + x[b1 + 8];
    }
}

// ---------------------------------------------------------------------------
extern "C" void kernel_launch(void* const* d_in, const int* in_sizes, int n_in,
                              void* d_out, int out_size) {
    const float* x     = (const float*)d_in[0];
    const float* Wq    = (const float*)d_in[1];
    const float* bq    = (const float*)d_in[2];
    const float* Wk    = (const float*)d_in[3];
    const float* bk    = (const float*)d_in[4];
    const float* Wv    = (const float*)d_in[5];
    const float* bv    = (const float*)d_in[6];
    const float* Wr    = (const float*)d_in[7];
    const float* gamma = (const float*)d_in[9];
    float* out = (float*)d_out;

    cudaFuncSetAttribute(proj_gemm_mma, cudaFuncAttributeMaxDynamicSharedMemorySize, PROJ_SMEM);
    cudaFuncSetAttribute(fused_attn, cudaFuncAttributeMaxDynamicSharedMemorySize, FUSED_SMEM);

    prep_kernel<<<384, CCH>>>(Wq, bq, Wk, bk, Wv, bv);
    proj_gemm_mma<<<dim3(NPIX / 128, 3, BATCH), 256, PROJ_SMEM>>>(x);
    augment_kernel<<<(BATCH * NPIX) / 256, 256>>>(Wr);
    fused_attn<<<dim3(NPIX / IB, BATCH), 512, FUSED_SMEM>>>(x, gamma, out);
}

// round 8
// speedup vs baseline: 4.4243x; 1.2331x over previous
#include <cuda_runtime.h>
#include <cuda_bf16.h>
#include <math.h>
#include <cstdint>

// Problem constants
#define BATCH 8
#define CCH   256
#define NPIX  1024
#define DHEAD 32
#define OC_ALL 320          // 32 q + 32 k + 256 v
#define KA    40            // augmented K padded to 40 (34 used)
#define ASTR2 44            // row stride for q'/k' (conflict-free tf32 frags)

// Scratch (device globals)
__device__ __nv_bfloat16 g_Vb[BATCH * CCH * NPIX];       // V projections, bf16
__device__ float g_qa[BATCH * NPIX * ASTR2];             // augmented scaled q rows (tf32)
__device__ float g_ka[BATCH * NPIX * ASTR2];             // augmented k rows (tf32)

// ===========================================================================
// helpers
// ===========================================================================
__device__ __forceinline__ float f2tf32(float f) {
    uint32_t u;
    asm("cvt.rna.tf32.f32 %0, %1;" : "=r"(u) : "f"(f));
    return __uint_as_float(u);
}
__device__ __forceinline__ float4 cvt4(float4 v) {
    v.x = f2tf32(v.x); v.y = f2tf32(v.y); v.z = f2tf32(v.z); v.w = f2tf32(v.w);
    return v;
}
__device__ __forceinline__ void mma_tf32(float* d, const uint32_t* a, const uint32_t* b) {
    asm volatile(
        "mma.sync.aligned.m16n8k8.row.col.f32.tf32.tf32.f32 "
        "{%0,%1,%2,%3}, {%4,%5,%6,%7}, {%8,%9}, {%0,%1,%2,%3};\n"
        : "+f"(d[0]), "+f"(d[1]), "+f"(d[2]), "+f"(d[3])
        : "r"(a[0]), "r"(a[1]), "r"(a[2]), "r"(a[3]), "r"(b[0]), "r"(b[1]));
}
__device__ __forceinline__ void mma_bf16(float* d, const uint32_t* a, const uint32_t* b) {
    asm volatile(
        "mma.sync.aligned.m16n8k16.row.col.f32.bf16.bf16.f32 "
        "{%0,%1,%2,%3}, {%4,%5,%6,%7}, {%8,%9}, {%0,%1,%2,%3};\n"
        : "+f"(d[0]), "+f"(d[1]), "+f"(d[2]), "+f"(d[3])
        : "r"(a[0]), "r"(a[1]), "r"(a[2]), "r"(a[3]), "r"(b[0]), "r"(b[1]));
}

// ---------------------------------------------------------------------------
// 1) Projection GEMM (tf32 mma), weights read directly (prep folded in):
//    rows 0..63 (q,k) -> smem -> augmented g_qa/g_ka (augment folded in)
//    rows 64..319 (v) -> g_Vb (bf16)
// ---------------------------------------------------------------------------
#define ASTR 36
#define BSTR_P 136
#define QK_LD 132
#define PROJ_SMEM_FLOATS (2 * 128 * ASTR + 2 * 32 * BSTR_P)     // 17920
#define PROJ_SMEM (PROJ_SMEM_FLOATS * (int)sizeof(float))       // 71680 (> QK reuse 33792)

__global__ __launch_bounds__(256) void proj_gemm_mma(const float* __restrict__ x,
                                                     const float* __restrict__ Wq,
                                                     const float* __restrict__ bq,
                                                     const float* __restrict__ Wk,
                                                     const float* __restrict__ bk,
                                                     const float* __restrict__ Wv,
                                                     const float* __restrict__ bv,
                                                     const float* __restrict__ Wr) {
    int b  = blockIdx.z;
    int m0 = blockIdx.y * 128;
    int n0 = blockIdx.x * 128;
    const float* X = x + (size_t)b * CCH * NPIX;

    extern __shared__ float sm[];
    float* As = sm;
    float* Bs = sm + 2 * 128 * ASTR;

    int tid = threadIdx.x, warp = tid >> 5, lane = tid & 31;
    int wm = warp >> 2, wn = warp & 3;
    int g = lane >> 2, tg = lane & 3;

    float acc[4][4][4];
    #pragma unroll
    for (int i = 0; i < 4; i++)
        #pragma unroll
        for (int j = 0; j < 4; j++)
            #pragma unroll
            for (int r = 0; r < 4; r++) acc[i][j][r] = 0.f;

    int arow[4], akq[4], brow[4], bnq[4];
    const float* wbase[4];
    #pragma unroll
    for (int u = 0; u < 4; u++) {
        int idx = tid + u * 256;
        arow[u] = idx >> 3;  akq[u] = (idx & 7) * 4;
        brow[u] = idx >> 5;  bnq[u] = (idx & 31) * 4;
        int r = m0 + arow[u];
        if (r < 32)       wbase[u] = Wq + (size_t)r * CCH;
        else if (r < 64)  wbase[u] = Wk + (size_t)(r - 32) * CCH;
        else if (r < 320) wbase[u] = Wv + (size_t)(r - 64) * CCH;
        else              wbase[u] = nullptr;
    }

    float4 pa[4], pb[4];
    #pragma unroll
    for (int u = 0; u < 4; u++) {
        pa[u] = wbase[u] ? *(const float4*)&wbase[u][akq[u]] : make_float4(0.f, 0.f, 0.f, 0.f);
        pb[u] = *(const float4*)&X[(size_t)brow[u] * NPIX + n0 + bnq[u]];
    }
    #pragma unroll
    for (int u = 0; u < 4; u++) {
        *(float4*)&As[arow[u] * ASTR + akq[u]]   = cvt4(pa[u]);
        *(float4*)&Bs[brow[u] * BSTR_P + bnq[u]] = cvt4(pb[u]);
    }
    __syncthreads();

    #pragma unroll 1
    for (int t = 0; t < 8; t++) {
        if (t < 7) {
            int k0 = (t + 1) * 32;
            #pragma unroll
            for (int u = 0; u < 4; u++) {
                pa[u] = wbase[u] ? *(const float4*)&wbase[u][k0 + akq[u]]
                                 : make_float4(0.f, 0.f, 0.f, 0.f);
                pb[u] = *(const float4*)&X[(size_t)(k0 + brow[u]) * NPIX + n0 + bnq[u]];
            }
        }
        const float* A = As + (t & 1) * 128 * ASTR;
        const float* B = Bs + (t & 1) * 32 * BSTR_P;
        #pragma unroll
        for (int kk = 0; kk < 32; kk += 8) {
            uint32_t af[4][4], bf[4][2];
            #pragma unroll
            for (int mt = 0; mt < 4; mt++) {
                int r = wm * 64 + mt * 16 + g;
                af[mt][0] = __float_as_uint(A[r * ASTR + kk + tg]);
                af[mt][1] = __float_as_uint(A[(r + 8) * ASTR + kk + tg]);
                af[mt][2] = __float_as_uint(A[r * ASTR + kk + tg + 4]);
                af[mt][3] = __float_as_uint(A[(r + 8) * ASTR + kk + tg + 4]);
            }
            #pragma unroll
            for (int nt = 0; nt < 4; nt++) {
                int nc = wn * 32 + nt * 8 + g;
                bf[nt][0] = __float_as_uint(B[(kk + tg) * BSTR_P + nc]);
                bf[nt][1] = __float_as_uint(B[(kk + tg + 4) * BSTR_P + nc]);
            }
            #pragma unroll
            for (int mt = 0; mt < 4; mt++)
                #pragma unroll
                for (int nt = 0; nt < 4; nt++)
                    mma_tf32(acc[mt][nt], af[mt], bf[nt]);
        }
        if (t < 7) {
            float* An = As + ((t + 1) & 1) * 128 * ASTR;
            float* Bn = Bs + ((t + 1) & 1) * 32 * BSTR_P;
            #pragma unroll
            for (int u = 0; u < 4; u++) {
                *(float4*)&An[arow[u] * ASTR + akq[u]]   = cvt4(pa[u]);
                *(float4*)&Bn[brow[u] * BSTR_P + bnq[u]] = cvt4(pb[u]);
            }
        }
        __syncthreads();
    }

    // epilogue: q,k rows (<64) -> smem QKs; v rows -> g_Vb bf16
    float* QKs = sm;   // reuse (64 x 132 floats = 33792 < 71680)
    #pragma unroll
    for (int mt = 0; mt < 4; mt++) {
        int rbase = m0 + wm * 64 + mt * 16 + g;
        #pragma unroll
        for (int half = 0; half < 2; half++) {
            int r = rbase + half * 8;
            if (r >= OC_ALL) continue;
            float bias = (r < 32) ? bq[r] : (r < 64) ? bk[r - 32] : bv[r - 64];
            #pragma unroll
            for (int nt = 0; nt < 4; nt++) {
                int cl = wn * 32 + nt * 8 + 2 * tg;
                float v0 = acc[mt][nt][half * 2 + 0] + bias;
                float v1 = acc[mt][nt][half * 2 + 1] + bias;
                if (r < 64) {
                    QKs[r * QK_LD + cl]     = v0;
                    QKs[r * QK_LD + cl + 1] = v1;
                } else {
                    *(__nv_bfloat162*)&g_Vb[((size_t)b * CCH + (r - 64)) * NPIX + n0 + cl] =
                        __floats2bfloat162_rn(v0, v1);
                }
            }
        }
    }
    if (m0 != 0) return;
    __syncthreads();

    // augment (m-tile 0 only): 128 threads, one pixel each
    if (tid < 128) {
        int n = n0 + tid;
        float a0 = 0.f, a1 = 0.f;
        float q[DHEAD];
        #pragma unroll
        for (int d = 0; d < DHEAD; d++) {
            q[d] = QKs[d * QK_LD + tid];
            a0 += q[d] * Wr[2 * d];
            a1 += q[d] * Wr[2 * d + 1];
        }
        const float scale = rsqrtf((float)DHEAD);
        float* qrow = g_qa + (size_t)(b * NPIX + n) * ASTR2;
        #pragma unroll
        for (int d = 0; d < DHEAD; d++) qrow[d] = f2tf32(q[d] * scale);
        qrow[32] = f2tf32(a0 * scale);
        qrow[33] = f2tf32(a1 * scale);
        #pragma unroll
        for (int d = 34; d < KA; d++) qrow[d] = 0.f;

        float* krow = g_ka + (size_t)(b * NPIX + n) * ASTR2;
        #pragma unroll
        for (int d = 0; d < DHEAD; d++) krow[d] = f2tf32(QKs[(32 + d) * QK_LD + tid]);
        int hi = n >> 5, wi = n & 31;
        krow[32] = f2tf32(-(float)hi * (1.f / 31.f));
        krow[33] = f2tf32(-(float)wi * (1.f / 31.f));
        #pragma unroll
        for (int d = 34; d < KA; d++) krow[d] = 0.f;
    }
}

// ---------------------------------------------------------------------------
// 2) Fused attention: logits tf32 mma -> exp (no-max) -> bf16 AV mma -> out
//    CTA = (64 i-rows, batch), 512 threads; warp grid 2(i) x 8(j/ch).
// ---------------------------------------------------------------------------
#define IB 64
#define JT 128
#define PSTRH 136
// byte offsets in dynamic smem
#define QS_B 0
#define KS_B (QS_B + IB * ASTR2 * 4)            // 11264
#define PS_B (KS_B + JT * ASTR2 * 4)            // 33792
#define VS_B (PS_B + IB * PSTRH * 2)            // 51200
#define RS_B (VS_B + CCH * PSTRH * 2)           // 120832
#define RI_B (RS_B + IB * 4)
#define FUSED_SMEM (RI_B + IB * 4)

__global__ __launch_bounds__(512) void fused_attn(const float* __restrict__ x,
                                                  const float* __restrict__ gamma,
                                                  float* __restrict__ out) {
    int b  = blockIdx.y;
    int i0 = blockIdx.x * IB;
    const float* qab = g_qa + (size_t)b * NPIX * ASTR2;
    const float* kab = g_ka + (size_t)b * NPIX * ASTR2;
    const __nv_bfloat16* Vg = g_Vb + (size_t)b * CCH * NPIX;

    extern __shared__ char smc[];
    float* Qs = (float*)(smc + QS_B);
    float* Ks = (float*)(smc + KS_B);
    __nv_bfloat16* PsH = (__nv_bfloat16*)(smc + PS_B);
    __nv_bfloat16* VsH = (__nv_bfloat16*)(smc + VS_B);
    float* rs = (float*)(smc + RS_B);
    float* ri = (float*)(smc + RI_B);

    int tid = threadIdx.x, warp = tid >> 5, lane = tid & 31;
    int wq = warp >> 3, wr = warp & 7;          // 2 (i) x 8 (j/ch) warp grid
    int g = lane >> 2, tg = lane & 3;

    if (tid < IB) rs[tid] = 0.f;

    // stage Qs (64 x 40 fp32, stride 44)
    for (int idx = tid; idx < 640; idx += 512) {
        int row = idx / 10, c4 = (idx % 10) * 4;
        *(float4*)&Qs[row * ASTR2 + c4] = *(const float4*)&qab[(size_t)(i0 + row) * ASTR2 + c4];
    }

    float accO[2][4][4];
    #pragma unroll
    for (int mt = 0; mt < 2; mt++)
        #pragma unroll
        for (int nt = 0; nt < 4; nt++)
            #pragma unroll
            for (int r = 0; r < 4; r++) accO[mt][nt][r] = 0.f;
    float s[2][2] = {{0.f, 0.f}, {0.f, 0.f}};

    #pragma unroll 1
    for (int jt = 0; jt < 8; jt++) {
        int j0 = jt * JT;
        // stage Ks (128 x 40 fp32)
        for (int idx = tid; idx < 1280; idx += 512) {
            int row = idx / 10, c4 = (idx % 10) * 4;
            *(float4*)&Ks[row * ASTR2 + c4] = *(const float4*)&kab[(size_t)(j0 + row) * ASTR2 + c4];
        }
        // prefetch V tile (256 ch x 128 j, bf16) into registers
        uint4 pv[8];
        #pragma unroll
        for (int u = 0; u < 8; u++) {
            int idx = tid + u * 512;
            int row = idx >> 4, q8 = (idx & 15) * 8;
            pv[u] = *(const uint4*)&Vg[(size_t)row * NPIX + j0 + q8];
        }
        __syncthreads();   // Ks visible; prev AV fully done

        // logits: 64 x 128, K=40 (tf32). Warp: m32 (2 x m16) x n16 (2 x n8)
        float accS[2][2][4];
        #pragma unroll
        for (int mt = 0; mt < 2; mt++)
            #pragma unroll
            for (int nt = 0; nt < 2; nt++)
                #pragma unroll
                for (int r = 0; r < 4; r++) accS[mt][nt][r] = 0.f;
        #pragma unroll
        for (int k = 0; k < 5; k++) {
            int kk = k * 8;
            uint32_t af[2][4];
            #pragma unroll
            for (int mt = 0; mt < 2; mt++) {
                int abase = (wq * 32 + mt * 16 + g) * ASTR2 + kk + tg;
                af[mt][0] = __float_as_uint(Qs[abase]);
                af[mt][1] = __float_as_uint(Qs[abase + 8 * ASTR2]);
                af[mt][2] = __float_as_uint(Qs[abase + 4]);
                af[mt][3] = __float_as_uint(Qs[abase + 8 * ASTR2 + 4]);
            }
            #pragma unroll
            for (int nt = 0; nt < 2; nt++) {
                uint32_t bf[2];
                int bb = (wr * 16 + nt * 8 + g) * ASTR2 + kk + tg;
                bf[0] = __float_as_uint(Ks[bb]);
                bf[1] = __float_as_uint(Ks[bb + 4]);
                #pragma unroll
                for (int mt = 0; mt < 2; mt++)
                    mma_tf32(accS[mt][nt], af[mt], bf);
            }
        }

        // exp + rowsum + write Ps (bf16 pairs)
        #pragma unroll
        for (int mt = 0; mt < 2; mt++) {
            int r0l = wq * 32 + mt * 16 + g;
            #pragma unroll
            for (int nt = 0; nt < 2; nt++) {
                float e0 = __expf(accS[mt][nt][0]);
                float e1 = __expf(accS[mt][nt][1]);
                float e2 = __expf(accS[mt][nt][2]);
                float e3 = __expf(accS[mt][nt][3]);
                s[mt][0] += e0 + e1; s[mt][1] += e2 + e3;
                int c = wr * 16 + nt * 8 + 2 * tg;
                *(__nv_bfloat162*)&PsH[r0l * PSTRH + c]       = __floats2bfloat162_rn(e0, e1);
                *(__nv_bfloat162*)&PsH[(r0l + 8) * PSTRH + c] = __floats2bfloat162_rn(e2, e3);
            }
        }
        __syncthreads();   // Ps visible

        // store V tile to smem
        #pragma unroll
        for (int u = 0; u < 8; u++) {
            int idx = tid + u * 512;
            int row = idx >> 4, q8 = (idx & 15) * 8;
            *(uint4*)&VsH[row * PSTRH + q8] = pv[u];
        }
        __syncthreads();   // Vs visible

        // AV: 64 x 256 += Ps(64x128) @ Vs(256x128)^T, bf16 k16
        // Warp: m32 (2 x m16) x n32 (4 x n8, ch = wr*32)
        #pragma unroll
        for (int kk = 0; kk < 128; kk += 16) {
            uint32_t af[2][4];
            #pragma unroll
            for (int mt = 0; mt < 2; mt++) {
                const __nv_bfloat16* pA = PsH + (wq * 32 + mt * 16 + g) * PSTRH + kk + 2 * tg;
                af[mt][0] = *(const uint32_t*)(pA);
                af[mt][1] = *(const uint32_t*)(pA + 8 * PSTRH);
                af[mt][2] = *(const uint32_t*)(pA + 8);
                af[mt][3] = *(const uint32_t*)(pA + 8 * PSTRH + 8);
            }
            #pragma unroll
            for (int nt = 0; nt < 4; nt++) {
                uint32_t bf[2];
                const __nv_bfloat16* pB = VsH + (wr * 32 + nt * 8 + g) * PSTRH + kk + 2 * tg;
                bf[0] = *(const uint32_t*)(pB);
                bf[1] = *(const uint32_t*)(pB + 8);
                #pragma unroll
                for (int mt = 0; mt < 2; mt++)
                    mma_bf16(accO[mt][nt], af[mt], bf);
            }
        }
    }

    // finalize row sums: reduce tg lanes, accumulate across wr warps
    #pragma unroll
    for (int mt = 0; mt < 2; mt++)
        #pragma unroll
        for (int h = 0; h < 2; h++) {
            float v = s[mt][h];
            v += __shfl_xor_sync(0xffffffffu, v, 1);
            v += __shfl_xor_sync(0xffffffffu, v, 2);
            if (tg == 0) atomicAdd(&rs[wq * 32 + mt * 16 + h * 8 + g], v);
        }
    __syncthreads();
    if (tid < IB) ri[tid] = gamma[0] / rs[tid];
    __syncthreads();

    // epilogue: out[b,c,i] = ri[i] * acc + x[b,c,i]
    #pragma unroll
    for (int mt = 0; mt < 2; mt++) {
        int r0l = wq * 32 + mt * 16 + g;
        float inv0 = ri[r0l], inv1 = ri[r0l + 8];
        #pragma unroll
        for (int nt = 0; nt < 4; nt++) {
            int ch = wr * 32 + nt * 8 + 2 * tg;
            size_t b0 = ((size_t)b * CCH + ch) * NPIX + i0 + r0l;
            size_t b1 = b0 + NPIX;                 // ch+1
            out[b0]     = accO[mt][nt][0] * inv0 + x[b0];
            out[b1]     = accO[mt][nt][1] * inv0 + x[b1];
            out[b0 + 8] = accO[mt][nt][2] * inv1 + x[b0 + 8];
            out[b1 + 8] = accO[mt][nt][3] * inv1 + x[b1 + 8];
        }
    }
}

// ---------------------------------------------------------------------------
extern "C" void kernel_launch(void* const* d_in, const int* in_sizes, int n_in,
                              void* d_out, int out_size) {
    const float* x     = (const float*)d_in[0];
    const float* Wq    = (const float*)d_in[1];
    const float* bq    = (const float*)d_in[2];
    const float* Wk    = (const float*)d_in[3];
    const float* bk    = (const float*)d_in[4];
    const float* Wv    = (const float*)d_in[5];
    const float* bv    = (const float*)d_in[6];
    const float* Wr    = (const float*)d_in[7];
    const float* gamma = (const float*)d_in[9];
    float* out = (float*)d_out;

    cudaFuncSetAttribute(proj_gemm_mma, cudaFuncAttributeMaxDynamicSharedMemorySize, PROJ_SMEM);
    cudaFuncSetAttribute(fused_attn, cudaFuncAttributeMaxDynamicSharedMemorySize, FUSED_SMEM);

    proj_gemm_mma<<<dim3(NPIX / 128, 3, BATCH), 256, PROJ_SMEM>>>(x, Wq, bq, Wk, bk, Wv, bv, Wr);
    fused_attn<<<dim3(NPIX / IB, BATCH), 512, FUSED_SMEM>>>(x, gamma, out);
}